// round 14
// baseline (speedup 1.0000x reference)
#include <cuda_runtime.h>
#include <cuda_bf16.h>
#include <math.h>
#include <stdint.h>

#define BB 4
#define CC 128
#define NN 16384   // 16*32*32
#define MM 2048    // 8*16*16
#define D1 32
#define D2 64
#define LOG2E 1.4426950408889634f

// Scratch (device globals; no allocations allowed)
__device__ __align__(16) __nv_bfloat16 g_theta[(size_t)BB * NN * D1]; // [b][n][d1] (pre-scaled by log2e)
__device__ __align__(16) __nv_bfloat16 g_fg[(size_t)BB * NN * D1];    // pre-pool phi
__device__ __align__(16) __nv_bfloat16 g_gh[(size_t)BB * NN * D2];    // pre-pool g
__device__ __align__(16) __nv_bfloat16 g_phi[(size_t)BB * MM * D1];   // [b][m][d1]
__device__ __align__(16) __nv_bfloat16 g_gpT[(size_t)BB * D2 * MM];   // [b][d][m]  TRANSPOSED
__device__ __align__(16) __nv_bfloat16 g_ag[(size_t)BB * NN * D2];    // attn out [b][n][d2]

__device__ __forceinline__ float to_tf32(float f) {
    uint32_t u;
    asm("cvt.rna.tf32.f32 %0, %1;" : "=r"(u) : "f"(f));
    return __uint_as_float(u);
}

__device__ __forceinline__ uint32_t ex2_bf16x2(uint32_t a) {
    uint32_t y;
    asm("ex2.approx.ftz.bf16x2 %0, %1;" : "=r"(y) : "r"(a));
    return y;
}

__device__ __forceinline__ void mma_tf32(float c[4],
    uint32_t a0, uint32_t a1, uint32_t a2, uint32_t a3,
    uint32_t b0, uint32_t b1)
{
    asm volatile(
        "mma.sync.aligned.m16n8k8.row.col.f32.tf32.tf32.f32 "
        "{%0,%1,%2,%3}, {%4,%5,%6,%7}, {%8,%9}, {%0,%1,%2,%3};"
        : "+f"(c[0]), "+f"(c[1]), "+f"(c[2]), "+f"(c[3])
        : "r"(a0), "r"(a1), "r"(a2), "r"(a3), "r"(b0), "r"(b1));
}

__device__ __forceinline__ void mma_bf16(float c[4],
    uint32_t a0, uint32_t a1, uint32_t a2, uint32_t a3,
    uint32_t b0, uint32_t b1)
{
    asm volatile(
        "mma.sync.aligned.m16n8k16.row.col.f32.bf16.bf16.f32 "
        "{%0,%1,%2,%3}, {%4,%5,%6,%7}, {%8,%9}, {%0,%1,%2,%3};"
        : "+f"(c[0]), "+f"(c[1]), "+f"(c[2]), "+f"(c[3])
        : "r"(a0), "r"(a1), "r"(a2), "r"(a3), "r"(b0), "r"(b1));
}

__device__ __forceinline__ void ldm_x4(uint32_t& r0, uint32_t& r1,
                                       uint32_t& r2, uint32_t& r3, uint32_t addr)
{
    asm volatile("ldmatrix.sync.aligned.m8n8.x4.shared.b16 {%0,%1,%2,%3}, [%4];"
        : "=r"(r0), "=r"(r1), "=r"(r2), "=r"(r3) : "r"(addr));
}

__device__ __forceinline__ void ldm_x2(uint32_t& r0, uint32_t& r1, uint32_t addr)
{
    asm volatile("ldmatrix.sync.aligned.m8n8.x2.shared.b16 {%0,%1}, [%2];"
        : "=r"(r0), "=r"(r1) : "r"(addr));
}

__device__ __forceinline__ uint32_t packbf(float x, float y) {
    __nv_bfloat162 h = __floats2bfloat162_rn(x, y);
    return *(uint32_t*)&h;
}

__device__ __forceinline__ void cp16(uint32_t smem_addr, const void* gptr) {
    asm volatile("cp.async.cg.shared.global [%0], [%1], 16;"
        :: "r"(smem_addr), "l"(gptr));
}
#define CP_COMMIT() asm volatile("cp.async.commit_group;")
#define CP_WAIT1()  asm volatile("cp.async.wait_group 1;")
#define CP_WAIT0()  asm volatile("cp.async.wait_group 0;")

// ---------------------------------------------------------------------------
// Kernel A (tf32 mma): fused 1x1 convs + ReLU -> bf16 outputs.
//   Y[n][o] = x^T[n][k] @ W^T[k][o].  wf/bf pre-scaled by log2e.
// ---------------------------------------------------------------------------
#define WS_STR 132
#define XS_STR 136
#define XSB (32 * XS_STR)

__global__ __launch_bounds__(256, 2) void k_conv(
    const float* __restrict__ x,
    const float* __restrict__ wf, const float* __restrict__ bf,
    const float* __restrict__ wg, const float* __restrict__ bg,
    const float* __restrict__ wh, const float* __restrict__ bh)
{
    extern __shared__ float sm[];
    float* ws = sm;                    // [128][132]
    float* bs = ws + 128 * WS_STR;     // [128]
    float* xs = bs + 128;              // 2 x [32][136]

    const int b   = blockIdx.y;
    const int n0  = blockIdx.x * 128;
    const int tid = threadIdx.x;
    const int warp = tid >> 5, lane = tid & 31;
    const int lq = lane >> 2;
    const int kq = lane & 3;
    const int qa = warp * 16 + lq;

#pragma unroll
    for (int it = 0; it < 16; it++) {
        int idx = tid + it * 256;
        int o = idx >> 5, k4 = idx & 31;
        float4 v; float scl = 1.f;
        if (o < 32)      { v = *(const float4*)&wf[o * 128 + k4 * 4]; scl = LOG2E; }
        else if (o < 64) v = *(const float4*)&wg[(o - 32) * 128 + k4 * 4];
        else             v = *(const float4*)&wh[(o - 64) * 128 + k4 * 4];
        v.x = to_tf32(v.x * scl); v.y = to_tf32(v.y * scl);
        v.z = to_tf32(v.z * scl); v.w = to_tf32(v.w * scl);
        *(float4*)&ws[o * WS_STR + k4 * 4] = v;
    }
    if (tid < 128) {
        bs[tid] = (tid < 32) ? bf[tid] * LOG2E
                : (tid < 64) ? bg[tid - 32] : bh[tid - 64];
    }

    const float* xb = x + (size_t)b * CC * NN;
    const uint32_t xs_u = (uint32_t)__cvta_generic_to_shared(xs);

#pragma unroll
    for (int it = 0; it < 4; it++) {
        int idx = tid + it * 256;
        int kk = idx >> 5, n4 = idx & 31;
        cp16(xs_u + (kk * XS_STR + n4 * 4) * 4,
             &xb[(size_t)kk * NN + n0 + n4 * 4]);
    }
    CP_COMMIT();

    float acc[16][4];
#pragma unroll
    for (int nt = 0; nt < 16; nt++)
#pragma unroll
        for (int j = 0; j < 4; j++) acc[nt][j] = 0.f;

    for (int c = 0; c < 4; c++) {
        int cur = c & 1;
        if (c < 3) {
            int k0n = (c + 1) * 32;
            uint32_t dst = xs_u + (cur ^ 1) * XSB * 4;
#pragma unroll
            for (int it = 0; it < 4; it++) {
                int idx = tid + it * 256;
                int kk = idx >> 5, n4 = idx & 31;
                cp16(dst + (kk * XS_STR + n4 * 4) * 4,
                     &xb[(size_t)(k0n + kk) * NN + n0 + n4 * 4]);
            }
            CP_COMMIT();
            CP_WAIT1();
        } else {
            CP_WAIT0();
        }
        __syncthreads();

        const float* xsc = xs + cur * XSB;
        const int k0 = c * 32;
#pragma unroll
        for (int kt = 0; kt < 4; kt++) {
            int kb = kt * 8 + kq;
            uint32_t a0 = __float_as_uint(xsc[kb * XS_STR + qa]);
            uint32_t a1 = __float_as_uint(xsc[kb * XS_STR + qa + 8]);
            uint32_t a2 = __float_as_uint(xsc[(kb + 4) * XS_STR + qa]);
            uint32_t a3 = __float_as_uint(xsc[(kb + 4) * XS_STR + qa + 8]);
            int kg = k0 + kb;
#pragma unroll
            for (int nt = 0; nt < 16; nt++) {
                int ob = nt * 8 + lq;
                uint32_t b0 = __float_as_uint(ws[ob * WS_STR + kg]);
                uint32_t b1 = __float_as_uint(ws[ob * WS_STR + kg + 4]);
                mma_tf32(acc[nt], a0, a1, a2, a3, b0, b1);
            }
        }
        __syncthreads();
    }

    const int na = n0 + qa;
#pragma unroll
    for (int nt = 0; nt < 16; nt++) {
        int o0 = nt * 8 + 2 * kq;
        float bias0 = bs[o0], bias1 = bs[o0 + 1];
        uint32_t r0 = packbf(fmaxf(acc[nt][0] + bias0, 0.f),
                             fmaxf(acc[nt][1] + bias1, 0.f));
        uint32_t r1 = packbf(fmaxf(acc[nt][2] + bias0, 0.f),
                             fmaxf(acc[nt][3] + bias1, 0.f));
        if (o0 < 32) {
            *(uint32_t*)&g_theta[((size_t)b * NN + na) * D1 + o0] = r0;
            *(uint32_t*)&g_theta[((size_t)b * NN + na + 8) * D1 + o0] = r1;
        } else if (o0 < 64) {
            *(uint32_t*)&g_fg[((size_t)b * NN + na) * D1 + o0 - 32] = r0;
            *(uint32_t*)&g_fg[((size_t)b * NN + na + 8) * D1 + o0 - 32] = r1;
        } else {
            *(uint32_t*)&g_gh[((size_t)b * NN + na) * D2 + o0 - 64] = r0;
            *(uint32_t*)&g_gh[((size_t)b * NN + na + 8) * D2 + o0 - 64] = r1;
        }
    }
}

// ---------------------------------------------------------------------------
// Kernel B: fused pooling.  Blocks 0-127: phi pool; blocks 128-255: g pool+T.
// ---------------------------------------------------------------------------
__global__ __launch_bounds__(256) void k_pool()
{
    const int tid = threadIdx.x;
    if (blockIdx.x < 128) {
        int idx = blockIdx.x * 256 + tid;   // BB*MM*4 = 32768
        int c8 = idx & 3;
        int m  = (idx >> 2) & (MM - 1);
        int b  = idx >> 13;
        int t2 = m >> 8, h2 = (m >> 4) & 15, w2 = m & 15;
        __nv_bfloat162 neg = __float2bfloat162_rn(-1e30f);
        __nv_bfloat162 r0 = neg, r1 = neg, r2 = neg, r3 = neg;
#pragma unroll
        for (int dt = 0; dt < 2; dt++)
#pragma unroll
            for (int dh = 0; dh < 2; dh++)
#pragma unroll
                for (int dw = 0; dw < 2; dw++) {
                    int n = (2 * t2 + dt) * 1024 + (2 * h2 + dh) * 32 + (2 * w2 + dw);
                    uint4 u = *(const uint4*)&g_fg[((size_t)b * NN + n) * D1 + c8 * 8];
                    const __nv_bfloat162* v = (const __nv_bfloat162*)&u;
                    r0 = __hmax2(r0, v[0]); r1 = __hmax2(r1, v[1]);
                    r2 = __hmax2(r2, v[2]); r3 = __hmax2(r3, v[3]);
                }
        uint4 o;
        ((__nv_bfloat162*)&o)[0] = r0; ((__nv_bfloat162*)&o)[1] = r1;
        ((__nv_bfloat162*)&o)[2] = r2; ((__nv_bfloat162*)&o)[3] = r3;
        *(uint4*)&g_phi[((size_t)b * MM + m) * D1 + c8 * 8] = o;
    } else {
        __shared__ __nv_bfloat16 gsm[64][66];
        const int bid = blockIdx.x - 128;
        const int b  = bid >> 5;
        const int mt = bid & 31;
        const int m0 = mt * 64;

#pragma unroll
        for (int it = 0; it < 8; it++) {
            int item = tid + it * 256;
            int ml = item >> 5, d2 = item & 31;
            int m = m0 + ml;
            int t2 = m >> 8, h2 = (m >> 4) & 15, w2 = m & 15;
            __nv_bfloat162 r = __float2bfloat162_rn(-1e30f);
#pragma unroll
            for (int dt = 0; dt < 2; dt++)
#pragma unroll
                for (int dh = 0; dh < 2; dh++)
#pragma unroll
                    for (int dw = 0; dw < 2; dw++) {
                        int n = (2 * t2 + dt) * 1024 + (2 * h2 + dh) * 32 + (2 * w2 + dw);
                        __nv_bfloat162 v = *(const __nv_bfloat162*)
                            &g_gh[((size_t)b * NN + n) * D2 + d2 * 2];
                        r = __hmax2(r, v);
                    }
            *(__nv_bfloat162*)&gsm[ml][d2 * 2] = r;
        }
        __syncthreads();
#pragma unroll
        for (int it = 0; it < 8; it++) {
            int item = tid + it * 256;
            int d = item >> 5, mw = item & 31;
            __nv_bfloat162 v;
            v.x = gsm[2 * mw][d];
            v.y = gsm[2 * mw + 1][d];
            *(__nv_bfloat162*)&g_gpT[((size_t)b * D2 + d) * MM + m0 + 2 * mw] = v;
        }
    }
}

// ---------------------------------------------------------------------------
// Kernel C: flash attention.  32 q/warp, 256-key quad-tile per barrier
// (2-stage ring of 4x64-key sub-buffers; no sync between sub-tiles).
// bf16 mma + ldmatrix, register-resident P, hoisted theta frags, bf16x2
// ex2, tensor-core row sums via ones-row.  CTA = 256 thr / 8 warps.
// ---------------------------------------------------------------------------
#define ATS 40   // theta/phi row stride (bf16)
#define GTS 72   // gT row stride (bf16); rows 0-63 = g, 64 = ones, 65-71 = 0
#define SHIFT2 5.0f                  // log2-domain shift
#define BUFE (64 * ATS + 72 * GTS)   // one 64-key sub-buffer (bf16): 7744
#define BUFB (BUFE * 2)              // bytes: 15488
#define GST_REL (64 * ATS * 2)       // byte offset of gT within a sub-buffer
#define BQ 256                       // queries per CTA
#define NSUB 4                       // sub-tiles per barrier (256 keys)

__global__ __launch_bounds__(256, 1) void k_attn()
{
    extern __shared__ __nv_bfloat16 smb[];
    __nv_bfloat16* ths = smb;                 // [256][40]
    __nv_bfloat16* stg = ths + BQ * ATS;      // 8 sub-buffers (2 stages x 4)

    const int b   = blockIdx.y;
    const int q0  = blockIdx.x * BQ;
    const int tid = threadIdx.x;
    const int warp = tid >> 5, lane = tid & 31;
    const int lq  = lane >> 2;
    const int kq  = lane & 3;

    // stage theta [256][32] bf16
#pragma unroll
    for (int it = 0; it < 4; it++) {
        int idx = tid + it * 256;             // [0,1024)
        int q = idx >> 2, k8 = idx & 3;
        *(uint4*)&ths[q * ATS + k8 * 8] =
            *(const uint4*)&g_theta[((size_t)b * NN + q0 + q) * D1 + k8 * 8];
    }

    // init ones-row (row 64 of gT region) + zero rows 65-71, all 8 sub-bufs
    {
        int r = tid >> 5, c = tid & 31;                 // 8 rows x 32 words
        uint32_t val = (r == 0) ? 0x3F803F80u : 0u;     // bf16 1.0 pair
#pragma unroll
        for (int p = 0; p < 2 * NSUB; p++)
            *(uint32_t*)&stg[p * BUFE + 64 * ATS + (64 + r) * GTS + c * 2] = val;
    }

    const uint32_t stg_u = (uint32_t)__cvta_generic_to_shared(stg);

    // per-thread staging coords (phi: 256 threads cover [64][32])
    const int sm_m = tid >> 2, sm_k8 = tid & 3;
    const uint32_t phs_off = (sm_m * ATS + sm_k8 * 8) * 2;
    const __nv_bfloat16* phi_src = &g_phi[((size_t)b * MM + sm_m) * D1 + sm_k8 * 8];
    // gT: 512 items [64][64]
    const int gd0 = tid >> 3, gm0 = (tid & 7) * 8;
    const uint32_t gst_off0 = GST_REL + (gd0 * GTS + gm0) * 2;
    const uint32_t gst_off1 = GST_REL + ((gd0 + 32) * GTS + gm0) * 2;
    const __nv_bfloat16* gT_src0 = &g_gpT[((size_t)b * D2 + gd0) * MM + gm0];
    const __nv_bfloat16* gT_src1 = &g_gpT[((size_t)b * D2 + gd0 + 32) * MM + gm0];

    // ldmatrix lane addresses
    const int mi = lane >> 3, mr = lane & 7;
    const uint32_t ths_u = (uint32_t)__cvta_generic_to_shared(ths);
    uint32_t aaddr[2];
#pragma unroll
    for (int h = 0; h < 2; h++)
        aaddr[h] = ths_u +
            ((warp * 32 + h * 16 + mr + (mi & 1) * 8) * ATS + (mi >> 1) * 8) * 2;
    const uint32_t b1rel = ((mr + (mi >> 1) * 8) * ATS + (mi & 1) * 8) * 2;
    const uint32_t b2rel = GST_REL + ((mr + (mi >> 1) * 8) * GTS + (mi & 1) * 8) * 2;
    const uint32_t lones_rel = GST_REL + ((64 + mr) * GTS + (mi & 1) * 8) * 2;

    // prologue: stage 256-key tile 0 into stage 0 (subs 0-3)
#pragma unroll
    for (int j = 0; j < NSUB; j++) {
        uint32_t off = j * BUFB;
        int m0 = j * 64;
        cp16(stg_u + off + phs_off, phi_src + (size_t)m0 * D1);
        cp16(stg_u + off + gst_off0, gT_src0 + m0);
        cp16(stg_u + off + gst_off1, gT_src1 + m0);
    }
    CP_COMMIT();

    // hoist theta A-fragments (loop-invariant): [h][kt][4]
    __syncthreads();
    uint32_t tha[2][2][4];
#pragma unroll
    for (int h = 0; h < 2; h++) {
        ldm_x4(tha[h][0][0], tha[h][0][1], tha[h][0][2], tha[h][0][3], aaddr[h]);
        ldm_x4(tha[h][1][0], tha[h][1][1], tha[h][1][2], tha[h][1][3], aaddr[h] + 32);
    }

    float oacc[2][8][4];
#pragma unroll
    for (int h = 0; h < 2; h++)
#pragma unroll
        for (int nt = 0; nt < 8; nt++)
#pragma unroll
            for (int j = 0; j < 4; j++) oacc[h][nt][j] = 0.f;
    float oaccL[2][4] = {{0.f,0.f,0.f,0.f},{0.f,0.f,0.f,0.f}};

    for (int t = 0; t < MM / (64 * NSUB); t++) {     // 8 iterations
        const int cur = t & 1;
        CP_WAIT0();
        __syncthreads();

        // prefetch next 256-key tile into the other stage (safe post-barrier)
        if (t < MM / (64 * NSUB) - 1) {
            uint32_t nbase = (cur ^ 1) * (NSUB * BUFB);
#pragma unroll
            for (int j = 0; j < NSUB; j++) {
                uint32_t off = nbase + j * BUFB;
                int m0 = (t + 1) * (64 * NSUB) + j * 64;
                cp16(stg_u + off + phs_off, phi_src + (size_t)m0 * D1);
                cp16(stg_u + off + gst_off0, gT_src0 + m0);
                cp16(stg_u + off + gst_off1, gT_src1 + m0);
            }
            CP_COMMIT();
        }

        // process NSUB 64-key sub-tiles with NO intervening barrier
#pragma unroll
        for (int j = 0; j < NSUB; j++) {
            const uint32_t coff = cur * (NSUB * BUFB) + j * BUFB;
            const uint32_t b1c = stg_u + coff + b1rel;
            const uint32_t b2c = stg_u + coff + b2rel;
            const uint32_t boc = stg_u + coff + lones_rel;

            // GEMM1: S[32q][64m], K=32; acc pre-loaded with -SHIFT2
            float s[2][8][4];
#pragma unroll
            for (int h = 0; h < 2; h++)
#pragma unroll
                for (int nt = 0; nt < 8; nt++)
#pragma unroll
                    for (int jj = 0; jj < 4; jj++) s[h][nt][jj] = -SHIFT2;

#pragma unroll
            for (int kt = 0; kt < 2; kt++) {
#pragma unroll
                for (int np = 0; np < 4; np++) {
                    uint32_t b0, b1, b2, b3;
                    ldm_x4(b0, b1, b2, b3, b1c + np * (16 * ATS * 2) + kt * 32);
#pragma unroll
                    for (int h = 0; h < 2; h++) {
                        mma_bf16(s[h][2 * np],
                                 tha[h][kt][0], tha[h][kt][1], tha[h][kt][2], tha[h][kt][3], b0, b1);
                        mma_bf16(s[h][2 * np + 1],
                                 tha[h][kt][0], tha[h][kt][1], tha[h][kt][2], tha[h][kt][3], b2, b3);
                    }
                }
            }

            // P = 2^s via bf16x2 MUFU (output IS the A fragment)
            uint32_t pa[2][8], pb[2][8];
#pragma unroll
            for (int h = 0; h < 2; h++)
#pragma unroll
                for (int nt = 0; nt < 8; nt++) {
                    pa[h][nt] = ex2_bf16x2(packbf(s[h][nt][0], s[h][nt][1]));
                    pb[h][nt] = ex2_bf16x2(packbf(s[h][nt][2], s[h][nt][3]));
                }

            // GEMM2: O[32q][64d] += P @ g ; ones-row gives row sums
#pragma unroll
            for (int kt = 0; kt < 4; kt++) {
#pragma unroll
                for (int np = 0; np < 4; np++) {
                    uint32_t b0, b1, b2, b3;
                    ldm_x4(b0, b1, b2, b3, b2c + np * (16 * GTS * 2) + kt * 32);
#pragma unroll
                    for (int h = 0; h < 2; h++) {
                        mma_bf16(oacc[h][2 * np],
                                 pa[h][2 * kt], pb[h][2 * kt],
                                 pa[h][2 * kt + 1], pb[h][2 * kt + 1], b0, b1);
                        mma_bf16(oacc[h][2 * np + 1],
                                 pa[h][2 * kt], pb[h][2 * kt],
                                 pa[h][2 * kt + 1], pb[h][2 * kt + 1], b2, b3);
                    }
                }
                uint32_t o0, o1;
                ldm_x2(o0, o1, boc + kt * 32);
#pragma unroll
                for (int h = 0; h < 2; h++)
                    mma_bf16(oaccL[h],
                             pa[h][2 * kt], pb[h][2 * kt],
                             pa[h][2 * kt + 1], pb[h][2 * kt + 1], o0, o1);
            }
        }
    }

    // row sums live in kq==0 lanes (col 64); broadcast within each quad
#pragma unroll
    for (int h = 0; h < 2; h++) {
        float l0 = __shfl_sync(0xffffffffu, oaccL[h][0], lane & ~3);
        float l1 = __shfl_sync(0xffffffffu, oaccL[h][2], lane & ~3);
        float inv0 = 1.f / l0;
        float inv1 = 1.f / l1;
        int qA = q0 + warp * 32 + h * 16 + lq;
        int qB = qA + 8;
#pragma unroll
        for (int nt = 0; nt < 8; nt++) {
            uint32_t w0 = packbf(oacc[h][nt][0] * inv0, oacc[h][nt][1] * inv0);
            uint32_t w1 = packbf(oacc[h][nt][2] * inv1, oacc[h][nt][3] * inv1);
            *(uint32_t*)&g_ag[((size_t)b * NN + qA) * D2 + nt * 8 + 2 * kq] = w0;
            *(uint32_t*)&g_ag[((size_t)b * NN + qB) * D2 + nt * 8 + 2 * kq] = w1;
        }
    }
}

// ---------------------------------------------------------------------------
// Kernel D (bf16 mma + ldmatrix): out = x + gamma * relu(wo @ attn_g + bo)
// Bias folded into acc init.  ags + full x tile prefetched via cp.async
// (x DRAM latency overlapped with ws staging + mma).  Epilogue transposes
// acc through smem (stride 68) and reads x from smem: coalesced float4 STG.
// ---------------------------------------------------------------------------
#define OT 72
#define YST 68   // fp32 staging row stride (68*4 = 272 B, 16B-aligned rows)
#define XBUF_ELE (2 * 128 * OT)   // bf16-element offset of xbuf (= 36864 B)

__global__ __launch_bounds__(256, 2) void k_out(
    const float* __restrict__ x,
    const float* __restrict__ wo, const float* __restrict__ bo,
    const float* __restrict__ gamma, float* __restrict__ out)
{
    extern __shared__ __nv_bfloat16 smo[];
    __nv_bfloat16* ws  = smo;               // [128][72]
    __nv_bfloat16* ags = ws + 128 * OT;     // [128][72]
    float* xbuf = (float*)(smo + XBUF_ELE); // [128 c][128 n] fp32 (64 KB)

    const int b   = blockIdx.y;
    const int n0  = blockIdx.x * 128;
    const int tid = threadIdx.x;
    const int warp = tid >> 5, lane = tid & 31;
    const int lq = lane >> 2;
    const int kq = lane & 3;
    const int ca = warp * 16 + lq;

    const uint32_t ags_u32 = (uint32_t)__cvta_generic_to_shared(ags);
    const uint32_t xbuf_u  = (uint32_t)__cvta_generic_to_shared(xbuf);
    const float* xb = &x[((size_t)b * CC) * NN + n0];

    // group A: ags via cp.async (already bf16 in gmem)
#pragma unroll
    for (int it = 0; it < 4; it++) {
        int idx = tid + it * 256;
        int n = idx >> 3, k8 = idx & 7;
        cp16(ags_u32 + (n * OT + k8 * 8) * 2,
             &g_ag[((size_t)b * NN + n0 + n) * D2 + k8 * 8]);
    }
    CP_COMMIT();
    // group B: full x tile [128 c][128 n] fp32 (consumed only in epilogue)
#pragma unroll
    for (int it = 0; it < 16; it++) {
        int idx = tid + it * 256;             // [0,4096)
        int c = idx >> 5, n16 = idx & 31;
        cp16(xbuf_u + (c * 128 + n16 * 4) * 4,
             xb + (size_t)c * NN + n16 * 4);
    }
    CP_COMMIT();

    // ws: LDG + cvt(fp32->bf16) + STS (overlaps cp.async groups)
#pragma unroll
    for (int it = 0; it < 8; it++) {
        int idx = tid + it * 256;
        int c = idx >> 4, k4 = idx & 15;
        float4 v = *(const float4*)&wo[c * 64 + k4 * 4];
        uint2 u;
        u.x = packbf(v.x, v.y);
        u.y = packbf(v.z, v.w);
        *(uint2*)&ws[c * OT + k4 * 4] = u;
    }

    const float bias0 = bo[ca];
    const float bias1 = bo[ca + 8];
    CP_WAIT1();        // ags complete (x may still be in flight)
    __syncthreads();

    const int mi = lane >> 3, mr = lane & 7;
    const uint32_t ws_u  = (uint32_t)__cvta_generic_to_shared(ws);
    const uint32_t aaddr = ws_u +
        ((warp * 16 + mr + (mi & 1) * 8) * OT + (mi >> 1) * 8) * 2;
    const uint32_t baddr = ags_u32 + ((mr + (mi >> 1) * 8) * OT + (mi & 1) * 8) * 2;

    float acc[16][4];
#pragma unroll
    for (int nt = 0; nt < 16; nt++) {
        acc[nt][0] = bias0; acc[nt][1] = bias0;
        acc[nt][2] = bias1; acc[nt][3] = bias1;
    }

#pragma unroll
    for (int kt = 0; kt < 4; kt++) {
        uint32_t a0, a1, a2, a3;
        ldm_x4(a0, a1, a2, a3, aaddr + kt * 32);
#pragma unroll
        for (int np = 0; np < 8; np++) {
            uint32_t b0, b1, b2, b3;
            ldm_x4(b0, b1, b2, b3, baddr + np * (16 * OT * 2) + kt * 32);
            mma_bf16(acc[2 * np],     a0, a1, a2, a3, b0, b1);
            mma_bf16(acc[2 * np + 1], a0, a1, a2, a3, b2, b3);
        }
    }

    const float gm = gamma[0];
    float* yst = (float*)smo;               // [128][68] overlays ws/ags (dead)

    CP_WAIT0();                             // x tile landed

    // two n-chunks of 64; stage gm*relu(acc) transposed, then coalesced x+y
#pragma unroll
    for (int j = 0; j < 2; j++) {
        __syncthreads();                    // protect smem reuse
#pragma unroll
        for (int nt8 = 0; nt8 < 8; nt8++) {
            int nt = j * 8 + nt8;
            int col = nt8 * 8 + 2 * kq;
            float2 v0, v1;
            v0.x = gm * fmaxf(acc[nt][0], 0.f);
            v0.y = gm * fmaxf(acc[nt][1], 0.f);
            v1.x = gm * fmaxf(acc[nt][2], 0.f);
            v1.y = gm * fmaxf(acc[nt][3], 0.f);
            *(float2*)&yst[ca * YST + col] = v0;
            *(float2*)&yst[(ca + 8) * YST + col] = v1;
        }
        __syncthreads();
#pragma unroll
        for (int it = 0; it < 8; it++) {
            int idx = tid + it * 256;       // [0,2048)
            int c = idx >> 4, n4 = idx & 15;
            float4 y  = *(float4*)&yst[c * YST + n4 * 4];
            float4 xv = *(float4*)&xbuf[c * 128 + j * 64 + n4 * 4];
            size_t go = ((size_t)b * CC + c) * NN + n0 + j * 64 + n4 * 4;
            float4 r;
            r.x = xv.x + y.x; r.y = xv.y + y.y;
            r.z = xv.z + y.z; r.w = xv.w + y.w;
            *(float4*)&out[go] = r;
        }
    }
}

// ---------------------------------------------------------------------------
extern "C" void kernel_launch(void* const* d_in, const int* in_sizes, int n_in,
                              void* d_out, int out_size)
{
    (void)in_sizes; (void)n_in; (void)out_size;
    const float* x  = (const float*)d_in[0];
    const float* wf = (const float*)d_in[1];
    const float* bf = (const float*)d_in[2];
    const float* wg = (const float*)d_in[3];
    const float* bg = (const float*)d_in[4];
    const float* wh = (const float*)d_in[5];
    const float* bh = (const float*)d_in[6];
    const float* wo = (const float*)d_in[7];
    const float* bo = (const float*)d_in[8];
    const float* gamma = (const float*)d_in[9];
    float* out = (float*)d_out;

    const int conv_smem = (128 * WS_STR + 128 + 2 * XSB) * 4;   // 102912
    const int attn_smem = BQ * ATS * 2 + 2 * NSUB * BUFB;       // 144384
    // k_out: bf16 tiles (36864 B, later overlaid by 34816 B fp32 yst)
    //        + 64 KB xbuf = 102400 B.  2 CTAs/SM: 204.8 KB < 228 KB.
    const int out_smem  = 2 * 128 * OT * 2 + 128 * 128 * 4;     // 102400
    cudaFuncSetAttribute(k_conv, cudaFuncAttributeMaxDynamicSharedMemorySize, conv_smem);
    cudaFuncSetAttribute(k_attn, cudaFuncAttributeMaxDynamicSharedMemorySize, attn_smem);
    cudaFuncSetAttribute(k_out,  cudaFuncAttributeMaxDynamicSharedMemorySize, out_smem);

    k_conv<<<dim3(NN / 128, BB), 256, conv_smem>>>(x, wf, bf, wg, bg, wh, bh);
    k_pool<<<256, 256>>>();
    k_attn<<<dim3(NN / BQ, BB), 256, attn_smem>>>();
    k_out<<<dim3(NN / 128, BB), 256, out_smem>>>(x, wo, bo, gamma, out);
}

// round 15
// speedup vs baseline: 1.0687x; 1.0687x over previous
#include <cuda_runtime.h>
#include <cuda_bf16.h>
#include <math.h>
#include <stdint.h>

#define BB 4
#define CC 128
#define NN 16384   // 16*32*32
#define MM 2048    // 8*16*16
#define D1 32
#define D2 64
#define LOG2E 1.4426950408889634f

// Scratch (device globals; no allocations allowed)
__device__ __align__(16) __nv_bfloat16 g_theta[(size_t)BB * NN * D1]; // [b][n][d1] (pre-scaled by log2e)
__device__ __align__(16) __nv_bfloat16 g_fg[(size_t)BB * NN * D1];    // pre-pool phi
__device__ __align__(16) __nv_bfloat16 g_gh[(size_t)BB * NN * D2];    // pre-pool g
__device__ __align__(16) __nv_bfloat16 g_phi[(size_t)BB * MM * D1];   // [b][m][d1]
__device__ __align__(16) __nv_bfloat16 g_gpT[(size_t)BB * D2 * MM];   // [b][d][m]  TRANSPOSED

__device__ __forceinline__ float to_tf32(float f) {
    uint32_t u;
    asm("cvt.rna.tf32.f32 %0, %1;" : "=r"(u) : "f"(f));
    return __uint_as_float(u);
}

__device__ __forceinline__ uint32_t ex2_bf16x2(uint32_t a) {
    uint32_t y;
    asm("ex2.approx.ftz.bf16x2 %0, %1;" : "=r"(y) : "r"(a));
    return y;
}

__device__ __forceinline__ void mma_tf32(float c[4],
    uint32_t a0, uint32_t a1, uint32_t a2, uint32_t a3,
    uint32_t b0, uint32_t b1)
{
    asm volatile(
        "mma.sync.aligned.m16n8k8.row.col.f32.tf32.tf32.f32 "
        "{%0,%1,%2,%3}, {%4,%5,%6,%7}, {%8,%9}, {%0,%1,%2,%3};"
        : "+f"(c[0]), "+f"(c[1]), "+f"(c[2]), "+f"(c[3])
        : "r"(a0), "r"(a1), "r"(a2), "r"(a3), "r"(b0), "r"(b1));
}

__device__ __forceinline__ void mma_bf16(float c[4],
    uint32_t a0, uint32_t a1, uint32_t a2, uint32_t a3,
    uint32_t b0, uint32_t b1)
{
    asm volatile(
        "mma.sync.aligned.m16n8k16.row.col.f32.bf16.bf16.f32 "
        "{%0,%1,%2,%3}, {%4,%5,%6,%7}, {%8,%9}, {%0,%1,%2,%3};"
        : "+f"(c[0]), "+f"(c[1]), "+f"(c[2]), "+f"(c[3])
        : "r"(a0), "r"(a1), "r"(a2), "r"(a3), "r"(b0), "r"(b1));
}

__device__ __forceinline__ void ldm_x4(uint32_t& r0, uint32_t& r1,
                                       uint32_t& r2, uint32_t& r3, uint32_t addr)
{
    asm volatile("ldmatrix.sync.aligned.m8n8.x4.shared.b16 {%0,%1,%2,%3}, [%4];"
        : "=r"(r0), "=r"(r1), "=r"(r2), "=r"(r3) : "r"(addr));
}

__device__ __forceinline__ void ldm_x2(uint32_t& r0, uint32_t& r1, uint32_t addr)
{
    asm volatile("ldmatrix.sync.aligned.m8n8.x2.shared.b16 {%0,%1}, [%2];"
        : "=r"(r0), "=r"(r1) : "r"(addr));
}

__device__ __forceinline__ uint32_t packbf(float x, float y) {
    __nv_bfloat162 h = __floats2bfloat162_rn(x, y);
    return *(uint32_t*)&h;
}

__device__ __forceinline__ void cp16(uint32_t smem_addr, const void* gptr) {
    asm volatile("cp.async.cg.shared.global [%0], [%1], 16;"
        :: "r"(smem_addr), "l"(gptr));
}
#define CP_COMMIT() asm volatile("cp.async.commit_group;")
#define CP_WAIT1()  asm volatile("cp.async.wait_group 1;")
#define CP_WAIT0()  asm volatile("cp.async.wait_group 0;")

// ---------------------------------------------------------------------------
// Kernel A (tf32 mma): fused 1x1 convs + ReLU -> bf16 outputs.
//   Y[n][o] = x^T[n][k] @ W^T[k][o].  wf/bf pre-scaled by log2e.
// ---------------------------------------------------------------------------
#define WS_STR 132
#define XS_STR 136
#define XSB (32 * XS_STR)

__global__ __launch_bounds__(256, 2) void k_conv(
    const float* __restrict__ x,
    const float* __restrict__ wf, const float* __restrict__ bf,
    const float* __restrict__ wg, const float* __restrict__ bg,
    const float* __restrict__ wh, const float* __restrict__ bh)
{
    extern __shared__ float sm[];
    float* ws = sm;                    // [128][132]
    float* bs = ws + 128 * WS_STR;     // [128]
    float* xs = bs + 128;              // 2 x [32][136]

    const int b   = blockIdx.y;
    const int n0  = blockIdx.x * 128;
    const int tid = threadIdx.x;
    const int warp = tid >> 5, lane = tid & 31;
    const int lq = lane >> 2;
    const int kq = lane & 3;
    const int qa = warp * 16 + lq;

#pragma unroll
    for (int it = 0; it < 16; it++) {
        int idx = tid + it * 256;
        int o = idx >> 5, k4 = idx & 31;
        float4 v; float scl = 1.f;
        if (o < 32)      { v = *(const float4*)&wf[o * 128 + k4 * 4]; scl = LOG2E; }
        else if (o < 64) v = *(const float4*)&wg[(o - 32) * 128 + k4 * 4];
        else             v = *(const float4*)&wh[(o - 64) * 128 + k4 * 4];
        v.x = to_tf32(v.x * scl); v.y = to_tf32(v.y * scl);
        v.z = to_tf32(v.z * scl); v.w = to_tf32(v.w * scl);
        *(float4*)&ws[o * WS_STR + k4 * 4] = v;
    }
    if (tid < 128) {
        bs[tid] = (tid < 32) ? bf[tid] * LOG2E
                : (tid < 64) ? bg[tid - 32] : bh[tid - 64];
    }

    const float* xb = x + (size_t)b * CC * NN;
    const uint32_t xs_u = (uint32_t)__cvta_generic_to_shared(xs);

#pragma unroll
    for (int it = 0; it < 4; it++) {
        int idx = tid + it * 256;
        int kk = idx >> 5, n4 = idx & 31;
        cp16(xs_u + (kk * XS_STR + n4 * 4) * 4,
             &xb[(size_t)kk * NN + n0 + n4 * 4]);
    }
    CP_COMMIT();

    float acc[16][4];
#pragma unroll
    for (int nt = 0; nt < 16; nt++)
#pragma unroll
        for (int j = 0; j < 4; j++) acc[nt][j] = 0.f;

    for (int c = 0; c < 4; c++) {
        int cur = c & 1;
        if (c < 3) {
            int k0n = (c + 1) * 32;
            uint32_t dst = xs_u + (cur ^ 1) * XSB * 4;
#pragma unroll
            for (int it = 0; it < 4; it++) {
                int idx = tid + it * 256;
                int kk = idx >> 5, n4 = idx & 31;
                cp16(dst + (kk * XS_STR + n4 * 4) * 4,
                     &xb[(size_t)(k0n + kk) * NN + n0 + n4 * 4]);
            }
            CP_COMMIT();
            CP_WAIT1();
        } else {
            CP_WAIT0();
        }
        __syncthreads();

        const float* xsc = xs + cur * XSB;
        const int k0 = c * 32;
#pragma unroll
        for (int kt = 0; kt < 4; kt++) {
            int kb = kt * 8 + kq;
            uint32_t a0 = __float_as_uint(xsc[kb * XS_STR + qa]);
            uint32_t a1 = __float_as_uint(xsc[kb * XS_STR + qa + 8]);
            uint32_t a2 = __float_as_uint(xsc[(kb + 4) * XS_STR + qa]);
            uint32_t a3 = __float_as_uint(xsc[(kb + 4) * XS_STR + qa + 8]);
            int kg = k0 + kb;
#pragma unroll
            for (int nt = 0; nt < 16; nt++) {
                int ob = nt * 8 + lq;
                uint32_t b0 = __float_as_uint(ws[ob * WS_STR + kg]);
                uint32_t b1 = __float_as_uint(ws[ob * WS_STR + kg + 4]);
                mma_tf32(acc[nt], a0, a1, a2, a3, b0, b1);
            }
        }
        __syncthreads();
    }

    const int na = n0 + qa;
#pragma unroll
    for (int nt = 0; nt < 16; nt++) {
        int o0 = nt * 8 + 2 * kq;
        float bias0 = bs[o0], bias1 = bs[o0 + 1];
        uint32_t r0 = packbf(fmaxf(acc[nt][0] + bias0, 0.f),
                             fmaxf(acc[nt][1] + bias1, 0.f));
        uint32_t r1 = packbf(fmaxf(acc[nt][2] + bias0, 0.f),
                             fmaxf(acc[nt][3] + bias1, 0.f));
        if (o0 < 32) {
            *(uint32_t*)&g_theta[((size_t)b * NN + na) * D1 + o0] = r0;
            *(uint32_t*)&g_theta[((size_t)b * NN + na + 8) * D1 + o0] = r1;
        } else if (o0 < 64) {
            *(uint32_t*)&g_fg[((size_t)b * NN + na) * D1 + o0 - 32] = r0;
            *(uint32_t*)&g_fg[((size_t)b * NN + na + 8) * D1 + o0 - 32] = r1;
        } else {
            *(uint32_t*)&g_gh[((size_t)b * NN + na) * D2 + o0 - 64] = r0;
            *(uint32_t*)&g_gh[((size_t)b * NN + na + 8) * D2 + o0 - 64] = r1;
        }
    }
}

// ---------------------------------------------------------------------------
// Kernel B: fused pooling.  Blocks 0-127: phi pool; blocks 128-255: g pool+T.
// ---------------------------------------------------------------------------
__global__ __launch_bounds__(256) void k_pool()
{
    const int tid = threadIdx.x;
    if (blockIdx.x < 128) {
        int idx = blockIdx.x * 256 + tid;   // BB*MM*4 = 32768
        int c8 = idx & 3;
        int m  = (idx >> 2) & (MM - 1);
        int b  = idx >> 13;
        int t2 = m >> 8, h2 = (m >> 4) & 15, w2 = m & 15;
        __nv_bfloat162 neg = __float2bfloat162_rn(-1e30f);
        __nv_bfloat162 r0 = neg, r1 = neg, r2 = neg, r3 = neg;
#pragma unroll
        for (int dt = 0; dt < 2; dt++)
#pragma unroll
            for (int dh = 0; dh < 2; dh++)
#pragma unroll
                for (int dw = 0; dw < 2; dw++) {
                    int n = (2 * t2 + dt) * 1024 + (2 * h2 + dh) * 32 + (2 * w2 + dw);
                    uint4 u = *(const uint4*)&g_fg[((size_t)b * NN + n) * D1 + c8 * 8];
                    const __nv_bfloat162* v = (const __nv_bfloat162*)&u;
                    r0 = __hmax2(r0, v[0]); r1 = __hmax2(r1, v[1]);
                    r2 = __hmax2(r2, v[2]); r3 = __hmax2(r3, v[3]);
                }
        uint4 o;
        ((__nv_bfloat162*)&o)[0] = r0; ((__nv_bfloat162*)&o)[1] = r1;
        ((__nv_bfloat162*)&o)[2] = r2; ((__nv_bfloat162*)&o)[3] = r3;
        *(uint4*)&g_phi[((size_t)b * MM + m) * D1 + c8 * 8] = o;
    } else {
        __shared__ __nv_bfloat16 gsm[64][66];
        const int bid = blockIdx.x - 128;
        const int b  = bid >> 5;
        const int mt = bid & 31;
        const int m0 = mt * 64;

#pragma unroll
        for (int it = 0; it < 8; it++) {
            int item = tid + it * 256;
            int ml = item >> 5, d2 = item & 31;
            int m = m0 + ml;
            int t2 = m >> 8, h2 = (m >> 4) & 15, w2 = m & 15;
            __nv_bfloat162 r = __float2bfloat162_rn(-1e30f);
#pragma unroll
            for (int dt = 0; dt < 2; dt++)
#pragma unroll
                for (int dh = 0; dh < 2; dh++)
#pragma unroll
                    for (int dw = 0; dw < 2; dw++) {
                        int n = (2 * t2 + dt) * 1024 + (2 * h2 + dh) * 32 + (2 * w2 + dw);
                        __nv_bfloat162 v = *(const __nv_bfloat162*)
                            &g_gh[((size_t)b * NN + n) * D2 + d2 * 2];
                        r = __hmax2(r, v);
                    }
            *(__nv_bfloat162*)&gsm[ml][d2 * 2] = r;
        }
        __syncthreads();
#pragma unroll
        for (int it = 0; it < 8; it++) {
            int item = tid + it * 256;
            int d = item >> 5, mw = item & 31;
            __nv_bfloat162 v;
            v.x = gsm[2 * mw][d];
            v.y = gsm[2 * mw + 1][d];
            *(__nv_bfloat162*)&g_gpT[((size_t)b * D2 + d) * MM + m0 + 2 * mw] = v;
        }
    }
}

// ---------------------------------------------------------------------------
// Kernel C: flash attention WITH FUSED OUTPUT CONV.
// 32 q/warp, 256-key quad-tile per barrier, bf16 mma + ldmatrix, register-
// resident P, hoisted theta frags + hoisted ones fragment, bf16x2 ex2,
// tensor-core row sums.  Epilogue: normalized O C-fragments double as the
// B operand of out = x + gm*relu(wo @ O^T + bo); A = wo via ldmatrix.
// ---------------------------------------------------------------------------
#define ATS 40   // theta/phi row stride (bf16)
#define GTS 72   // gT row stride (bf16); rows 0-63 = g, 64 = ones, 65-71 = 0
#define OT  72   // wo row stride (bf16)
#define SHIFT2 5.0f                  // log2-domain shift
#define BUFE (64 * ATS + 72 * GTS)   // one 64-key sub-buffer (bf16): 7744
#define BUFB (BUFE * 2)              // bytes: 15488
#define GST_REL (64 * ATS * 2)       // byte offset of gT within a sub-buffer
#define BQ 256                       // queries per CTA
#define NSUB 4                       // sub-tiles per barrier (256 keys)

__global__ __launch_bounds__(256, 1) void k_attn(
    const float* __restrict__ x,
    const float* __restrict__ wo, const float* __restrict__ bo,
    const float* __restrict__ gamma, float* __restrict__ out)
{
    extern __shared__ __nv_bfloat16 smb[];
    __nv_bfloat16* ths = smb;                     // [256][40]
    __nv_bfloat16* stg = ths + BQ * ATS;          // 8 sub-buffers
    __nv_bfloat16* wos = stg + 2 * NSUB * BUFE;   // [128][72]
    float* bosm = (float*)(wos + 128 * OT);       // [128]

    const int b   = blockIdx.y;
    const int q0  = blockIdx.x * BQ;
    const int tid = threadIdx.x;
    const int warp = tid >> 5, lane = tid & 31;
    const int lq  = lane >> 2;
    const int kq  = lane & 3;

    // stage theta [256][32] bf16
#pragma unroll
    for (int it = 0; it < 4; it++) {
        int idx = tid + it * 256;
        int q = idx >> 2, k8 = idx & 3;
        *(uint4*)&ths[q * ATS + k8 * 8] =
            *(const uint4*)&g_theta[((size_t)b * NN + q0 + q) * D1 + k8 * 8];
    }

    // stage wo -> bf16 [128][72] and bo -> bosm (for fused epilogue)
#pragma unroll
    for (int it = 0; it < 8; it++) {
        int idx = tid + it * 256;
        int c = idx >> 4, k4 = idx & 15;
        float4 v = *(const float4*)&wo[c * 64 + k4 * 4];
        uint2 u;
        u.x = packbf(v.x, v.y);
        u.y = packbf(v.z, v.w);
        *(uint2*)&wos[c * OT + k4 * 4] = u;
    }
    if (tid < 128) bosm[tid] = bo[tid];

    // init ones-row (row 64 of gT region) + zero rows 65-71, all 8 sub-bufs
    {
        int r = tid >> 5, c = tid & 31;
        uint32_t val = (r == 0) ? 0x3F803F80u : 0u;
#pragma unroll
        for (int p = 0; p < 2 * NSUB; p++)
            *(uint32_t*)&stg[p * BUFE + 64 * ATS + (64 + r) * GTS + c * 2] = val;
    }

    const uint32_t stg_u = (uint32_t)__cvta_generic_to_shared(stg);

    // per-thread staging coords
    const int sm_m = tid >> 2, sm_k8 = tid & 3;
    const uint32_t phs_off = (sm_m * ATS + sm_k8 * 8) * 2;
    const __nv_bfloat16* phi_src = &g_phi[((size_t)b * MM + sm_m) * D1 + sm_k8 * 8];
    const int gd0 = tid >> 3, gm0 = (tid & 7) * 8;
    const uint32_t gst_off0 = GST_REL + (gd0 * GTS + gm0) * 2;
    const uint32_t gst_off1 = GST_REL + ((gd0 + 32) * GTS + gm0) * 2;
    const __nv_bfloat16* gT_src0 = &g_gpT[((size_t)b * D2 + gd0) * MM + gm0];
    const __nv_bfloat16* gT_src1 = &g_gpT[((size_t)b * D2 + gd0 + 32) * MM + gm0];

    // ldmatrix lane addresses
    const int mi = lane >> 3, mr = lane & 7;
    const uint32_t ths_u = (uint32_t)__cvta_generic_to_shared(ths);
    uint32_t aaddr[2];
#pragma unroll
    for (int h = 0; h < 2; h++)
        aaddr[h] = ths_u +
            ((warp * 32 + h * 16 + mr + (mi & 1) * 8) * ATS + (mi >> 1) * 8) * 2;
    const uint32_t b1rel = ((mr + (mi >> 1) * 8) * ATS + (mi & 1) * 8) * 2;
    const uint32_t b2rel = GST_REL + ((mr + (mi >> 1) * 8) * GTS + (mi & 1) * 8) * 2;
    const uint32_t lones_rel = GST_REL + ((64 + mr) * GTS + (mi & 1) * 8) * 2;

    // prologue: stage 256-key tile 0 into stage 0 (subs 0-3)
#pragma unroll
    for (int j = 0; j < NSUB; j++) {
        uint32_t off = j * BUFB;
        int m0 = j * 64;
        cp16(stg_u + off + phs_off, phi_src + (size_t)m0 * D1);
        cp16(stg_u + off + gst_off0, gT_src0 + m0);
        cp16(stg_u + off + gst_off1, gT_src1 + m0);
    }
    CP_COMMIT();

    // hoist theta A-fragments + constant ones B-fragment
    __syncthreads();
    uint32_t tha[2][2][4];
#pragma unroll
    for (int h = 0; h < 2; h++) {
        ldm_x4(tha[h][0][0], tha[h][0][1], tha[h][0][2], tha[h][0][3], aaddr[h]);
        ldm_x4(tha[h][1][0], tha[h][1][1], tha[h][1][2], tha[h][1][3], aaddr[h] + 32);
    }
    uint32_t ones0, ones1;
    ldm_x2(ones0, ones1, stg_u + lones_rel);   // constant across all kt/tiles

    float oacc[2][8][4];
#pragma unroll
    for (int h = 0; h < 2; h++)
#pragma unroll
        for (int nt = 0; nt < 8; nt++)
#pragma unroll
            for (int j = 0; j < 4; j++) oacc[h][nt][j] = 0.f;
    float oaccL[2][4] = {{0.f,0.f,0.f,0.f},{0.f,0.f,0.f,0.f}};

    for (int t = 0; t < MM / (64 * NSUB); t++) {     // 8 iterations
        const int cur = t & 1;
        CP_WAIT0();
        __syncthreads();

        if (t < MM / (64 * NSUB) - 1) {
            uint32_t nbase = (cur ^ 1) * (NSUB * BUFB);
#pragma unroll
            for (int j = 0; j < NSUB; j++) {
                uint32_t off = nbase + j * BUFB;
                int m0 = (t + 1) * (64 * NSUB) + j * 64;
                cp16(stg_u + off + phs_off, phi_src + (size_t)m0 * D1);
                cp16(stg_u + off + gst_off0, gT_src0 + m0);
                cp16(stg_u + off + gst_off1, gT_src1 + m0);
            }
            CP_COMMIT();
        }

#pragma unroll
        for (int j = 0; j < NSUB; j++) {
            const uint32_t coff = cur * (NSUB * BUFB) + j * BUFB;
            const uint32_t b1c = stg_u + coff + b1rel;
            const uint32_t b2c = stg_u + coff + b2rel;

            float s[2][8][4];
#pragma unroll
            for (int h = 0; h < 2; h++)
#pragma unroll
                for (int nt = 0; nt < 8; nt++)
#pragma unroll
                    for (int jj = 0; jj < 4; jj++) s[h][nt][jj] = -SHIFT2;

#pragma unroll
            for (int kt = 0; kt < 2; kt++) {
#pragma unroll
                for (int np = 0; np < 4; np++) {
                    uint32_t b0, b1, b2, b3;
                    ldm_x4(b0, b1, b2, b3, b1c + np * (16 * ATS * 2) + kt * 32);
#pragma unroll
                    for (int h = 0; h < 2; h++) {
                        mma_bf16(s[h][2 * np],
                                 tha[h][kt][0], tha[h][kt][1], tha[h][kt][2], tha[h][kt][3], b0, b1);
                        mma_bf16(s[h][2 * np + 1],
                                 tha[h][kt][0], tha[h][kt][1], tha[h][kt][2], tha[h][kt][3], b2, b3);
                    }
                }
            }

            uint32_t pa[2][8], pb[2][8];
#pragma unroll
            for (int h = 0; h < 2; h++)
#pragma unroll
                for (int nt = 0; nt < 8; nt++) {
                    pa[h][nt] = ex2_bf16x2(packbf(s[h][nt][0], s[h][nt][1]));
                    pb[h][nt] = ex2_bf16x2(packbf(s[h][nt][2], s[h][nt][3]));
                }

#pragma unroll
            for (int kt = 0; kt < 4; kt++) {
#pragma unroll
                for (int np = 0; np < 4; np++) {
                    uint32_t b0, b1, b2, b3;
                    ldm_x4(b0, b1, b2, b3, b2c + np * (16 * GTS * 2) + kt * 32);
#pragma unroll
                    for (int h = 0; h < 2; h++) {
                        mma_bf16(oacc[h][2 * np],
                                 pa[h][2 * kt], pb[h][2 * kt],
                                 pa[h][2 * kt + 1], pb[h][2 * kt + 1], b0, b1);
                        mma_bf16(oacc[h][2 * np + 1],
                                 pa[h][2 * kt], pb[h][2 * kt],
                                 pa[h][2 * kt + 1], pb[h][2 * kt + 1], b2, b3);
                    }
                }
#pragma unroll
                for (int h = 0; h < 2; h++)
                    mma_bf16(oaccL[h],
                             pa[h][2 * kt], pb[h][2 * kt],
                             pa[h][2 * kt + 1], pb[h][2 * kt + 1], ones0, ones1);
            }
        }
    }

    // ---- fused output conv: out = x + gm*relu(wo @ O^T + bo) ----
    // normalized O C-fragments ARE the B-fragments: pB[h][r][kt] covers
    // n-tile (q rows warp*32 + h*16 + r*8 + 0..7), k = d in [16kt,16kt+16).
    uint32_t pB[2][2][4][2];
#pragma unroll
    for (int h = 0; h < 2; h++) {
        float l0 = __shfl_sync(0xffffffffu, oaccL[h][0], lane & ~3);
        float l1 = __shfl_sync(0xffffffffu, oaccL[h][2], lane & ~3);
        float inv0 = 1.f / l0;
        float inv1 = 1.f / l1;
#pragma unroll
        for (int kt = 0; kt < 4; kt++) {
            pB[h][0][kt][0] = packbf(oacc[h][2*kt][0]*inv0,   oacc[h][2*kt][1]*inv0);
            pB[h][0][kt][1] = packbf(oacc[h][2*kt+1][0]*inv0, oacc[h][2*kt+1][1]*inv0);
            pB[h][1][kt][0] = packbf(oacc[h][2*kt][2]*inv1,   oacc[h][2*kt][3]*inv1);
            pB[h][1][kt][1] = packbf(oacc[h][2*kt+1][2]*inv1, oacc[h][2*kt+1][3]*inv1);
        }
    }

    const float gm = gamma[0];
    const uint32_t wos_u = (uint32_t)__cvta_generic_to_shared(wos);
    const float* xg = x;

#pragma unroll
    for (int mt = 0; mt < 8; mt++) {
        float facc[4][4];
        float bv0 = bosm[mt * 16 + lq];
        float bv1 = bosm[mt * 16 + lq + 8];
#pragma unroll
        for (int g = 0; g < 4; g++) {
            facc[g][0] = bv0; facc[g][1] = bv0;
            facc[g][2] = bv1; facc[g][3] = bv1;
        }
        uint32_t fad = wos_u + ((mt * 16 + mr + (mi & 1) * 8) * OT + (mi >> 1) * 8) * 2;
#pragma unroll
        for (int kt = 0; kt < 4; kt++) {
            uint32_t a0, a1, a2, a3;
            ldm_x4(a0, a1, a2, a3, fad + kt * 32);
#pragma unroll
            for (int h = 0; h < 2; h++)
#pragma unroll
                for (int r = 0; r < 2; r++)
                    mma_bf16(facc[h * 2 + r], a0, a1, a2, a3,
                             pB[h][r][kt][0], pB[h][r][kt][1]);
        }
        // write out (C rows = channels mt*16+lq / +8, cols = n)
        int c0r = mt * 16 + lq, c1r = c0r + 8;
#pragma unroll
        for (int h = 0; h < 2; h++)
#pragma unroll
            for (int r = 0; r < 2; r++) {
                int g = h * 2 + r;
                size_t ncol = (size_t)q0 + warp * 32 + h * 16 + r * 8 + 2 * kq;
                size_t go0 = ((size_t)b * CC + c0r) * NN + ncol;
                size_t go1 = ((size_t)b * CC + c1r) * NN + ncol;
                float2 xv0 = *(const float2*)&xg[go0];
                float2 xv1 = *(const float2*)&xg[go1];
                float2 w0, w1;
                w0.x = xv0.x + gm * fmaxf(facc[g][0], 0.f);
                w0.y = xv0.y + gm * fmaxf(facc[g][1], 0.f);
                w1.x = xv1.x + gm * fmaxf(facc[g][2], 0.f);
                w1.y = xv1.y + gm * fmaxf(facc[g][3], 0.f);
                *(float2*)&out[go0] = w0;
                *(float2*)&out[go1] = w1;
            }
    }
}

// ---------------------------------------------------------------------------
extern "C" void kernel_launch(void* const* d_in, const int* in_sizes, int n_in,
                              void* d_out, int out_size)
{
    (void)in_sizes; (void)n_in; (void)out_size;
    const float* x  = (const float*)d_in[0];
    const float* wf = (const float*)d_in[1];
    const float* bf = (const float*)d_in[2];
    const float* wg = (const float*)d_in[3];
    const float* bg = (const float*)d_in[4];
    const float* wh = (const float*)d_in[5];
    const float* bh = (const float*)d_in[6];
    const float* wo = (const float*)d_in[7];
    const float* bo = (const float*)d_in[8];
    const float* gamma = (const float*)d_in[9];
    float* out = (float*)d_out;

    const int conv_smem = (128 * WS_STR + 128 + 2 * XSB) * 4;   // 102912
    const int attn_smem = (BQ * ATS + 2 * NSUB * BUFE + 128 * OT) * 2 + 128 * 4; // 163328
    cudaFuncSetAttribute(k_conv, cudaFuncAttributeMaxDynamicSharedMemorySize, conv_smem);
    cudaFuncSetAttribute(k_attn, cudaFuncAttributeMaxDynamicSharedMemorySize, attn_smem);

    k_conv<<<dim3(NN / 128, BB), 256, conv_smem>>>(x, wf, bf, wg, bg, wh, bh);
    k_pool<<<256, 256>>>();
    k_attn<<<dim3(NN / BQ, BB), 256, attn_smem>>>(x, wo, bo, gamma, out);
}

// round 16
// speedup vs baseline: 1.1230x; 1.0508x over previous
#include <cuda_runtime.h>
#include <cuda_bf16.h>
#include <math.h>
#include <stdint.h>

#define BB 4
#define CC 128
#define NN 16384   // 16*32*32
#define MM 2048    // 8*16*16
#define D1 32
#define D2 64
#define LOG2E 1.4426950408889634f

// Scratch (device globals; no allocations allowed)
__device__ __align__(16) __nv_bfloat16 g_theta[(size_t)BB * NN * D1]; // [b][n][d1] (pre-scaled by log2e)
__device__ __align__(16) __nv_bfloat16 g_fg[(size_t)BB * NN * D1];    // pre-pool phi
__device__ __align__(16) __nv_bfloat16 g_gh[(size_t)BB * NN * D2];    // pre-pool g
__device__ __align__(16) __nv_bfloat16 g_phi[(size_t)BB * MM * D1];   // [b][m][d1]
__device__ __align__(16) __nv_bfloat16 g_gpT[(size_t)BB * D2 * MM];   // [b][d][m]  TRANSPOSED

__device__ __forceinline__ uint32_t ex2_bf16x2(uint32_t a) {
    uint32_t y;
    asm("ex2.approx.ftz.bf16x2 %0, %1;" : "=r"(y) : "r"(a));
    return y;
}

__device__ __forceinline__ void mma_bf16(float c[4],
    uint32_t a0, uint32_t a1, uint32_t a2, uint32_t a3,
    uint32_t b0, uint32_t b1)
{
    asm volatile(
        "mma.sync.aligned.m16n8k16.row.col.f32.bf16.bf16.f32 "
        "{%0,%1,%2,%3}, {%4,%5,%6,%7}, {%8,%9}, {%0,%1,%2,%3};"
        : "+f"(c[0]), "+f"(c[1]), "+f"(c[2]), "+f"(c[3])
        : "r"(a0), "r"(a1), "r"(a2), "r"(a3), "r"(b0), "r"(b1));
}

__device__ __forceinline__ void ldm_x4(uint32_t& r0, uint32_t& r1,
                                       uint32_t& r2, uint32_t& r3, uint32_t addr)
{
    asm volatile("ldmatrix.sync.aligned.m8n8.x4.shared.b16 {%0,%1,%2,%3}, [%4];"
        : "=r"(r0), "=r"(r1), "=r"(r2), "=r"(r3) : "r"(addr));
}

__device__ __forceinline__ void ldm_x4t(uint32_t& r0, uint32_t& r1,
                                        uint32_t& r2, uint32_t& r3, uint32_t addr)
{
    asm volatile("ldmatrix.sync.aligned.m8n8.x4.trans.shared.b16 {%0,%1,%2,%3}, [%4];"
        : "=r"(r0), "=r"(r1), "=r"(r2), "=r"(r3) : "r"(addr));
}

__device__ __forceinline__ void ldm_x2(uint32_t& r0, uint32_t& r1, uint32_t addr)
{
    asm volatile("ldmatrix.sync.aligned.m8n8.x2.shared.b16 {%0,%1}, [%2];"
        : "=r"(r0), "=r"(r1) : "r"(addr));
}

__device__ __forceinline__ uint32_t packbf(float x, float y) {
    __nv_bfloat162 h = __floats2bfloat162_rn(x, y);
    return *(uint32_t*)&h;
}

__device__ __forceinline__ void cp16(uint32_t smem_addr, const void* gptr) {
    asm volatile("cp.async.cg.shared.global [%0], [%1], 16;"
        :: "r"(smem_addr), "l"(gptr));
}
#define CP_COMMIT() asm volatile("cp.async.commit_group;")
#define CP_WAIT0()  asm volatile("cp.async.wait_group 0;")

// ---------------------------------------------------------------------------
// Kernel A (bf16 mma + ldmatrix): fused 1x1 convs + ReLU -> bf16 outputs.
//   Y[n][o] = x^T[n][k] @ W^T[k][o]; wf/bf pre-scaled by log2e.
// x staged k-major bf16 [32k][136n] (coalesced STS.64); A-frags via
// ldmatrix.x4.trans; B (weights) [o][136k] via ldmatrix.x4.
// Register-double-buffered LDG pipeline; one barrier per k-chunk.
// ---------------------------------------------------------------------------
#define OT2 136   // weight row stride (bf16)
#define NTS 136   // x chunk row stride (bf16)
#define XCH (32 * NTS)

__global__ __launch_bounds__(256, 2) void k_conv(
    const float* __restrict__ x,
    const float* __restrict__ wf, const float* __restrict__ bf,
    const float* __restrict__ wg, const float* __restrict__ bg,
    const float* __restrict__ wh, const float* __restrict__ bh)
{
    extern __shared__ __nv_bfloat16 smc[];
    __nv_bfloat16* wos = smc;                 // [128][136]
    __nv_bfloat16* xs  = wos + 128 * OT2;     // 2 x [32][136]
    float* bs = (float*)(xs + 2 * XCH);       // [128]

    const int b   = blockIdx.y;
    const int n0  = blockIdx.x * 128;
    const int tid = threadIdx.x;
    const int warp = tid >> 5, lane = tid & 31;
    const int lq = lane >> 2;
    const int kq = lane & 3;
    const int qa = warp * 16 + lq;            // CTA-local n row

    // stage weights bf16 [o][k] (wf pre-scaled by log2e)
#pragma unroll
    for (int it = 0; it < 16; it++) {
        int idx = tid + it * 256;             // [0,4096) float4
        int o = idx >> 5, k4 = idx & 31;
        float4 v; float scl = 1.f;
        if (o < 32)      { v = *(const float4*)&wf[o * 128 + k4 * 4]; scl = LOG2E; }
        else if (o < 64) v = *(const float4*)&wg[(o - 32) * 128 + k4 * 4];
        else             v = *(const float4*)&wh[(o - 64) * 128 + k4 * 4];
        uint2 u;
        u.x = packbf(v.x * scl, v.y * scl);
        u.y = packbf(v.z * scl, v.w * scl);
        *(uint2*)&wos[o * OT2 + k4 * 4] = u;
    }
    if (tid < 128) {
        bs[tid] = (tid < 32) ? bf[tid] * LOG2E
                : (tid < 64) ? bg[tid - 32] : bh[tid - 64];
    }

    const float* xb = x + (size_t)b * CC * NN;
    const int skk = tid >> 5, sn4 = tid & 31;   // staging coords (4 items/thread)

    // prologue: LDG chunk 0 + STS -> buf 0
    float4 xr[4];
#pragma unroll
    for (int it = 0; it < 4; it++) {
        int kk = skk + it * 8;
        xr[it] = *(const float4*)&xb[(size_t)kk * NN + n0 + sn4 * 4];
    }
#pragma unroll
    for (int it = 0; it < 4; it++) {
        int kk = skk + it * 8;
        uint2 u;
        u.x = packbf(xr[it].x, xr[it].y);
        u.y = packbf(xr[it].z, xr[it].w);
        *(uint2*)&xs[kk * NTS + sn4 * 4] = u;
    }
    __syncthreads();

    // ldmatrix lane addresses
    const int mi = lane >> 3, mr = lane & 7;
    const uint32_t wos_u = (uint32_t)__cvta_generic_to_shared(wos);
    const uint32_t xs_u  = (uint32_t)__cvta_generic_to_shared(xs);
    // A (x, k-major, .trans): matrix mi -> k-half (mi>>1), n-half (mi&1)
    const uint32_t xarel = (((mi >> 1) * 8 + mr) * NTS + warp * 16 + (mi & 1) * 8) * 2;
    // B (weights, o-major): same mapping as fused epilogue
    const uint32_t wbrel = ((mr + (mi >> 1) * 8) * OT2 + (mi & 1) * 8) * 2;

    float acc[16][4];
#pragma unroll
    for (int nt = 0; nt < 16; nt++)
#pragma unroll
        for (int j = 0; j < 4; j++) acc[nt][j] = 0.f;

    for (int c = 0; c < 4; c++) {
        if (c < 3) {
            int k0n = (c + 1) * 32;
#pragma unroll
            for (int it = 0; it < 4; it++) {
                int kk = skk + it * 8;
                xr[it] = *(const float4*)&xb[(size_t)(k0n + kk) * NN + n0 + sn4 * 4];
            }
        }

        const uint32_t xc = xs_u + (c & 1) * (XCH * 2);
#pragma unroll
        for (int kt = 0; kt < 2; kt++) {      // k16 steps within chunk
            uint32_t a0, a1, a2, a3;
            ldm_x4t(a0, a1, a2, a3, xc + kt * (16 * NTS * 2) + xarel);
            int ktg = c * 2 + kt;             // global k16 index
#pragma unroll
            for (int np = 0; np < 8; np++) {
                uint32_t b0, b1, b2, b3;
                ldm_x4(b0, b1, b2, b3,
                       wos_u + wbrel + np * (16 * OT2 * 2) + ktg * 32);
                mma_bf16(acc[2 * np],     a0, a1, a2, a3, b0, b1);
                mma_bf16(acc[2 * np + 1], a0, a1, a2, a3, b2, b3);
            }
        }

        if (c < 3) {
            __nv_bfloat16* dst = xs + ((c + 1) & 1) * XCH;
#pragma unroll
            for (int it = 0; it < 4; it++) {
                int kk = skk + it * 8;
                uint2 u;
                u.x = packbf(xr[it].x, xr[it].y);
                u.y = packbf(xr[it].z, xr[it].w);
                *(uint2*)&dst[kk * NTS + sn4 * 4] = u;
            }
            __syncthreads();
        }
    }

    // epilogue: bias + relu, write bf16 to [n][d] layouts
    const int na = n0 + qa;
#pragma unroll
    for (int nt = 0; nt < 16; nt++) {
        int o0 = nt * 8 + 2 * kq;
        float bias0 = bs[o0], bias1 = bs[o0 + 1];
        uint32_t r0 = packbf(fmaxf(acc[nt][0] + bias0, 0.f),
                             fmaxf(acc[nt][1] + bias1, 0.f));
        uint32_t r1 = packbf(fmaxf(acc[nt][2] + bias0, 0.f),
                             fmaxf(acc[nt][3] + bias1, 0.f));
        if (o0 < 32) {
            *(uint32_t*)&g_theta[((size_t)b * NN + na) * D1 + o0] = r0;
            *(uint32_t*)&g_theta[((size_t)b * NN + na + 8) * D1 + o0] = r1;
        } else if (o0 < 64) {
            *(uint32_t*)&g_fg[((size_t)b * NN + na) * D1 + o0 - 32] = r0;
            *(uint32_t*)&g_fg[((size_t)b * NN + na + 8) * D1 + o0 - 32] = r1;
        } else {
            *(uint32_t*)&g_gh[((size_t)b * NN + na) * D2 + o0 - 64] = r0;
            *(uint32_t*)&g_gh[((size_t)b * NN + na + 8) * D2 + o0 - 64] = r1;
        }
    }
}

// ---------------------------------------------------------------------------
// Kernel B: fused pooling.  Blocks 0-127: phi pool; blocks 128-255: g pool+T.
// ---------------------------------------------------------------------------
__global__ __launch_bounds__(256) void k_pool()
{
    const int tid = threadIdx.x;
    if (blockIdx.x < 128) {
        int idx = blockIdx.x * 256 + tid;
        int c8 = idx & 3;
        int m  = (idx >> 2) & (MM - 1);
        int b  = idx >> 13;
        int t2 = m >> 8, h2 = (m >> 4) & 15, w2 = m & 15;
        __nv_bfloat162 neg = __float2bfloat162_rn(-1e30f);
        __nv_bfloat162 r0 = neg, r1 = neg, r2 = neg, r3 = neg;
#pragma unroll
        for (int dt = 0; dt < 2; dt++)
#pragma unroll
            for (int dh = 0; dh < 2; dh++)
#pragma unroll
                for (int dw = 0; dw < 2; dw++) {
                    int n = (2 * t2 + dt) * 1024 + (2 * h2 + dh) * 32 + (2 * w2 + dw);
                    uint4 u = *(const uint4*)&g_fg[((size_t)b * NN + n) * D1 + c8 * 8];
                    const __nv_bfloat162* v = (const __nv_bfloat162*)&u;
                    r0 = __hmax2(r0, v[0]); r1 = __hmax2(r1, v[1]);
                    r2 = __hmax2(r2, v[2]); r3 = __hmax2(r3, v[3]);
                }
        uint4 o;
        ((__nv_bfloat162*)&o)[0] = r0; ((__nv_bfloat162*)&o)[1] = r1;
        ((__nv_bfloat162*)&o)[2] = r2; ((__nv_bfloat162*)&o)[3] = r3;
        *(uint4*)&g_phi[((size_t)b * MM + m) * D1 + c8 * 8] = o;
    } else {
        __shared__ __nv_bfloat16 gsm[64][66];
        const int bid = blockIdx.x - 128;
        const int b  = bid >> 5;
        const int mt = bid & 31;
        const int m0 = mt * 64;

#pragma unroll
        for (int it = 0; it < 8; it++) {
            int item = tid + it * 256;
            int ml = item >> 5, d2 = item & 31;
            int m = m0 + ml;
            int t2 = m >> 8, h2 = (m >> 4) & 15, w2 = m & 15;
            __nv_bfloat162 r = __float2bfloat162_rn(-1e30f);
#pragma unroll
            for (int dt = 0; dt < 2; dt++)
#pragma unroll
                for (int dh = 0; dh < 2; dh++)
#pragma unroll
                    for (int dw = 0; dw < 2; dw++) {
                        int n = (2 * t2 + dt) * 1024 + (2 * h2 + dh) * 32 + (2 * w2 + dw);
                        __nv_bfloat162 v = *(const __nv_bfloat162*)
                            &g_gh[((size_t)b * NN + n) * D2 + d2 * 2];
                        r = __hmax2(r, v);
                    }
            *(__nv_bfloat162*)&gsm[ml][d2 * 2] = r;
        }
        __syncthreads();
#pragma unroll
        for (int it = 0; it < 8; it++) {
            int item = tid + it * 256;
            int d = item >> 5, mw = item & 31;
            __nv_bfloat162 v;
            v.x = gsm[2 * mw][d];
            v.y = gsm[2 * mw + 1][d];
            *(__nv_bfloat162*)&g_gpT[((size_t)b * D2 + d) * MM + m0 + 2 * mw] = v;
        }
    }
}

// ---------------------------------------------------------------------------
// Kernel C: flash attention WITH FUSED OUTPUT CONV (unchanged from R15).
// ---------------------------------------------------------------------------
#define ATS 40
#define GTS 72
#define OT  72
#define SHIFT2 5.0f
#define BUFE (64 * ATS + 72 * GTS)
#define BUFB (BUFE * 2)
#define GST_REL (64 * ATS * 2)
#define BQ 256
#define NSUB 4

__global__ __launch_bounds__(256, 1) void k_attn(
    const float* __restrict__ x,
    const float* __restrict__ wo, const float* __restrict__ bo,
    const float* __restrict__ gamma, float* __restrict__ out)
{
    extern __shared__ __nv_bfloat16 smb[];
    __nv_bfloat16* ths = smb;                     // [256][40]
    __nv_bfloat16* stg = ths + BQ * ATS;          // 8 sub-buffers
    __nv_bfloat16* wos = stg + 2 * NSUB * BUFE;   // [128][72]
    float* bosm = (float*)(wos + 128 * OT);       // [128]

    const int b   = blockIdx.y;
    const int q0  = blockIdx.x * BQ;
    const int tid = threadIdx.x;
    const int warp = tid >> 5, lane = tid & 31;
    const int lq  = lane >> 2;
    const int kq  = lane & 3;

#pragma unroll
    for (int it = 0; it < 4; it++) {
        int idx = tid + it * 256;
        int q = idx >> 2, k8 = idx & 3;
        *(uint4*)&ths[q * ATS + k8 * 8] =
            *(const uint4*)&g_theta[((size_t)b * NN + q0 + q) * D1 + k8 * 8];
    }

#pragma unroll
    for (int it = 0; it < 8; it++) {
        int idx = tid + it * 256;
        int c = idx >> 4, k4 = idx & 15;
        float4 v = *(const float4*)&wo[c * 64 + k4 * 4];
        uint2 u;
        u.x = packbf(v.x, v.y);
        u.y = packbf(v.z, v.w);
        *(uint2*)&wos[c * OT + k4 * 4] = u;
    }
    if (tid < 128) bosm[tid] = bo[tid];

    {
        int r = tid >> 5, c = tid & 31;
        uint32_t val = (r == 0) ? 0x3F803F80u : 0u;
#pragma unroll
        for (int p = 0; p < 2 * NSUB; p++)
            *(uint32_t*)&stg[p * BUFE + 64 * ATS + (64 + r) * GTS + c * 2] = val;
    }

    const uint32_t stg_u = (uint32_t)__cvta_generic_to_shared(stg);

    const int sm_m = tid >> 2, sm_k8 = tid & 3;
    const uint32_t phs_off = (sm_m * ATS + sm_k8 * 8) * 2;
    const __nv_bfloat16* phi_src = &g_phi[((size_t)b * MM + sm_m) * D1 + sm_k8 * 8];
    const int gd0 = tid >> 3, gm0 = (tid & 7) * 8;
    const uint32_t gst_off0 = GST_REL + (gd0 * GTS + gm0) * 2;
    const uint32_t gst_off1 = GST_REL + ((gd0 + 32) * GTS + gm0) * 2;
    const __nv_bfloat16* gT_src0 = &g_gpT[((size_t)b * D2 + gd0) * MM + gm0];
    const __nv_bfloat16* gT_src1 = &g_gpT[((size_t)b * D2 + gd0 + 32) * MM + gm0];

    const int mi = lane >> 3, mr = lane & 7;
    const uint32_t ths_u = (uint32_t)__cvta_generic_to_shared(ths);
    uint32_t aaddr[2];
#pragma unroll
    for (int h = 0; h < 2; h++)
        aaddr[h] = ths_u +
            ((warp * 32 + h * 16 + mr + (mi & 1) * 8) * ATS + (mi >> 1) * 8) * 2;
    const uint32_t b1rel = ((mr + (mi >> 1) * 8) * ATS + (mi & 1) * 8) * 2;
    const uint32_t b2rel = GST_REL + ((mr + (mi >> 1) * 8) * GTS + (mi & 1) * 8) * 2;
    const uint32_t lones_rel = GST_REL + ((64 + mr) * GTS + (mi & 1) * 8) * 2;

#pragma unroll
    for (int j = 0; j < NSUB; j++) {
        uint32_t off = j * BUFB;
        int m0 = j * 64;
        cp16(stg_u + off + phs_off, phi_src + (size_t)m0 * D1);
        cp16(stg_u + off + gst_off0, gT_src0 + m0);
        cp16(stg_u + off + gst_off1, gT_src1 + m0);
    }
    CP_COMMIT();

    __syncthreads();
    uint32_t tha[2][2][4];
#pragma unroll
    for (int h = 0; h < 2; h++) {
        ldm_x4(tha[h][0][0], tha[h][0][1], tha[h][0][2], tha[h][0][3], aaddr[h]);
        ldm_x4(tha[h][1][0], tha[h][1][1], tha[h][1][2], tha[h][1][3], aaddr[h] + 32);
    }
    uint32_t ones0, ones1;
    ldm_x2(ones0, ones1, stg_u + lones_rel);

    float oacc[2][8][4];
#pragma unroll
    for (int h = 0; h < 2; h++)
#pragma unroll
        for (int nt = 0; nt < 8; nt++)
#pragma unroll
            for (int j = 0; j < 4; j++) oacc[h][nt][j] = 0.f;
    float oaccL[2][4] = {{0.f,0.f,0.f,0.f},{0.f,0.f,0.f,0.f}};

    for (int t = 0; t < MM / (64 * NSUB); t++) {
        const int cur = t & 1;
        CP_WAIT0();
        __syncthreads();

        if (t < MM / (64 * NSUB) - 1) {
            uint32_t nbase = (cur ^ 1) * (NSUB * BUFB);
#pragma unroll
            for (int j = 0; j < NSUB; j++) {
                uint32_t off = nbase + j * BUFB;
                int m0 = (t + 1) * (64 * NSUB) + j * 64;
                cp16(stg_u + off + phs_off, phi_src + (size_t)m0 * D1);
                cp16(stg_u + off + gst_off0, gT_src0 + m0);
                cp16(stg_u + off + gst_off1, gT_src1 + m0);
            }
            CP_COMMIT();
        }

#pragma unroll
        for (int j = 0; j < NSUB; j++) {
            const uint32_t coff = cur * (NSUB * BUFB) + j * BUFB;
            const uint32_t b1c = stg_u + coff + b1rel;
            const uint32_t b2c = stg_u + coff + b2rel;

            float s[2][8][4];
#pragma unroll
            for (int h = 0; h < 2; h++)
#pragma unroll
                for (int nt = 0; nt < 8; nt++)
#pragma unroll
                    for (int jj = 0; jj < 4; jj++) s[h][nt][jj] = -SHIFT2;

#pragma unroll
            for (int kt = 0; kt < 2; kt++) {
#pragma unroll
                for (int np = 0; np < 4; np++) {
                    uint32_t b0, b1, b2, b3;
                    ldm_x4(b0, b1, b2, b3, b1c + np * (16 * ATS * 2) + kt * 32);
#pragma unroll
                    for (int h = 0; h < 2; h++) {
                        mma_bf16(s[h][2 * np],
                                 tha[h][kt][0], tha[h][kt][1], tha[h][kt][2], tha[h][kt][3], b0, b1);
                        mma_bf16(s[h][2 * np + 1],
                                 tha[h][kt][0], tha[h][kt][1], tha[h][kt][2], tha[h][kt][3], b2, b3);
                    }
                }
            }

            uint32_t pa[2][8], pb[2][8];
#pragma unroll
            for (int h = 0; h < 2; h++)
#pragma unroll
                for (int nt = 0; nt < 8; nt++) {
                    pa[h][nt] = ex2_bf16x2(packbf(s[h][nt][0], s[h][nt][1]));
                    pb[h][nt] = ex2_bf16x2(packbf(s[h][nt][2], s[h][nt][3]));
                }

#pragma unroll
            for (int kt = 0; kt < 4; kt++) {
#pragma unroll
                for (int np = 0; np < 4; np++) {
                    uint32_t b0, b1, b2, b3;
                    ldm_x4(b0, b1, b2, b3, b2c + np * (16 * GTS * 2) + kt * 32);
#pragma unroll
                    for (int h = 0; h < 2; h++) {
                        mma_bf16(oacc[h][2 * np],
                                 pa[h][2 * kt], pb[h][2 * kt],
                                 pa[h][2 * kt + 1], pb[h][2 * kt + 1], b0, b1);
                        mma_bf16(oacc[h][2 * np + 1],
                                 pa[h][2 * kt], pb[h][2 * kt],
                                 pa[h][2 * kt + 1], pb[h][2 * kt + 1], b2, b3);
                    }
                }
#pragma unroll
                for (int h = 0; h < 2; h++)
                    mma_bf16(oaccL[h],
                             pa[h][2 * kt], pb[h][2 * kt],
                             pa[h][2 * kt + 1], pb[h][2 * kt + 1], ones0, ones1);
            }
        }
    }

    // fused output conv
    uint32_t pB[2][2][4][2];
#pragma unroll
    for (int h = 0; h < 2; h++) {
        float l0 = __shfl_sync(0xffffffffu, oaccL[h][0], lane & ~3);
        float l1 = __shfl_sync(0xffffffffu, oaccL[h][2], lane & ~3);
        float inv0 = 1.f / l0;
        float inv1 = 1.f / l1;
#pragma unroll
        for (int kt = 0; kt < 4; kt++) {
            pB[h][0][kt][0] = packbf(oacc[h][2*kt][0]*inv0,   oacc[h][2*kt][1]*inv0);
            pB[h][0][kt][1] = packbf(oacc[h][2*kt+1][0]*inv0, oacc[h][2*kt+1][1]*inv0);
            pB[h][1][kt][0] = packbf(oacc[h][2*kt][2]*inv1,   oacc[h][2*kt][3]*inv1);
            pB[h][1][kt][1] = packbf(oacc[h][2*kt+1][2]*inv1, oacc[h][2*kt+1][3]*inv1);
        }
    }

    const float gm = gamma[0];
    const uint32_t wos_u = (uint32_t)__cvta_generic_to_shared(wos);
    const float* xg = x;

#pragma unroll
    for (int mt = 0; mt < 8; mt++) {
        float facc[4][4];
        float bv0 = bosm[mt * 16 + lq];
        float bv1 = bosm[mt * 16 + lq + 8];
#pragma unroll
        for (int g = 0; g < 4; g++) {
            facc[g][0] = bv0; facc[g][1] = bv0;
            facc[g][2] = bv1; facc[g][3] = bv1;
        }
        uint32_t fad = wos_u + ((mt * 16 + mr + (mi & 1) * 8) * OT + (mi >> 1) * 8) * 2;
#pragma unroll
        for (int kt = 0; kt < 4; kt++) {
            uint32_t a0, a1, a2, a3;
            ldm_x4(a0, a1, a2, a3, fad + kt * 32);
#pragma unroll
            for (int h = 0; h < 2; h++)
#pragma unroll
                for (int r = 0; r < 2; r++)
                    mma_bf16(facc[h * 2 + r], a0, a1, a2, a3,
                             pB[h][r][kt][0], pB[h][r][kt][1]);
        }
        int c0r = mt * 16 + lq, c1r = c0r + 8;
#pragma unroll
        for (int h = 0; h < 2; h++)
#pragma unroll
            for (int r = 0; r < 2; r++) {
                int g = h * 2 + r;
                size_t ncol = (size_t)q0 + warp * 32 + h * 16 + r * 8 + 2 * kq;
                size_t go0 = ((size_t)b * CC + c0r) * NN + ncol;
                size_t go1 = ((size_t)b * CC + c1r) * NN + ncol;
                float2 xv0 = *(const float2*)&xg[go0];
                float2 xv1 = *(const float2*)&xg[go1];
                float2 w0, w1;
                w0.x = xv0.x + gm * fmaxf(facc[g][0], 0.f);
                w0.y = xv0.y + gm * fmaxf(facc[g][1], 0.f);
                w1.x = xv1.x + gm * fmaxf(facc[g][2], 0.f);
                w1.y = xv1.y + gm * fmaxf(facc[g][3], 0.f);
                *(float2*)&out[go0] = w0;
                *(float2*)&out[go1] = w1;
            }
    }
}

// ---------------------------------------------------------------------------
extern "C" void kernel_launch(void* const* d_in, const int* in_sizes, int n_in,
                              void* d_out, int out_size)
{
    (void)in_sizes; (void)n_in; (void)out_size;
    const float* x  = (const float*)d_in[0];
    const float* wf = (const float*)d_in[1];
    const float* bf = (const float*)d_in[2];
    const float* wg = (const float*)d_in[3];
    const float* bg = (const float*)d_in[4];
    const float* wh = (const float*)d_in[5];
    const float* bh = (const float*)d_in[6];
    const float* wo = (const float*)d_in[7];
    const float* bo = (const float*)d_in[8];
    const float* gamma = (const float*)d_in[9];
    float* out = (float*)d_out;

    const int conv_smem = (128 * OT2 + 2 * XCH) * 2 + 128 * 4;  // 52736
    const int attn_smem = (BQ * ATS + 2 * NSUB * BUFE + 128 * OT) * 2 + 128 * 4; // 163328
    cudaFuncSetAttribute(k_conv, cudaFuncAttributeMaxDynamicSharedMemorySize, conv_smem);
    cudaFuncSetAttribute(k_attn, cudaFuncAttributeMaxDynamicSharedMemorySize, attn_smem);

    k_conv<<<dim3(NN / 128, BB), 256, conv_smem>>>(x, wf, bf, wg, bg, wh, bh);
    k_pool<<<256, 256>>>();
    k_attn<<<dim3(NN / BQ, BB), 256, attn_smem>>>(x, wo, bo, gamma, out);
}